// round 17
// baseline (speedup 1.0000x reference)
#include <cuda_runtime.h>
#include <cstdint>

// Problem constants
#define NN 40000
#define EE 640000
#define DD 128
#define EDD 16
#define LL 3
#define BN_INV 0.99999500003749978f  // 1/sqrt(1+1e-5)
#define DST 4   // edge-kernel smem pipeline depth

// Scratch (no cudaMalloc allowed)
__device__ float  g_h[(size_t)NN * DD];
__device__ float  g_h2[(size_t)NN * DD];
__device__ float  g_agg[(size_t)NN * DD];
__device__ float  g_t[(size_t)NN * 2 * DD];
__device__ float2 g_pre[NN];
__device__ int    g_deg[NN];
__device__ int    g_off[NN + 1];
__device__ int    g_cur[NN];
__device__ int    g_esrc[EE];   // src node id per CSR slot
__device__ int    g_eidx[EE];   // original edge id per CSR slot
// tf32 hi/lo split of all GEMM weights:
//  [0, 16384)       node_W ; [16384, 114688) W1[3] ; [114688, 212992) W2[3]
#define WSPLIT_TOTAL 212992
__device__ float g_whi[WSPLIT_TOTAL];
__device__ float g_wlo[WSPLIT_TOTAL];

// ---- f32x2 helpers --------------------------------------------------------
__device__ __forceinline__ unsigned long long pack2(float lo, float hi) {
    unsigned long long r;
    asm("mov.b64 %0, {%1, %2};" : "=l"(r) : "f"(lo), "f"(hi));
    return r;
}
__device__ __forceinline__ void ffma2(unsigned long long& d,
                                      unsigned long long a,
                                      unsigned long long b) {
    asm("fma.rn.f32x2 %0, %1, %2, %0;" : "+l"(d) : "l"(a), "l"(b));
}
__device__ __forceinline__ void unpack2(unsigned long long v, float& lo, float& hi) {
    asm("mov.b64 {%0, %1}, %2;" : "=f"(lo), "=f"(hi) : "l"(v));
}
__device__ __forceinline__ float fold2(unsigned long long v) {
    float lo, hi; unpack2(v, lo, hi); return lo + hi;
}

// ---- cp.async helper (16B, per-thread address) ----------------------------
__device__ __forceinline__ void cp16(void* smem_dst, const void* gmem_src) {
    uint32_t d = (uint32_t)__cvta_generic_to_shared(smem_dst);
    asm volatile("cp.async.cg.shared.global [%0], [%1], 16;"
                 :: "r"(d), "l"(gmem_src) : "memory");
}
#define CP_COMMIT() asm volatile("cp.async.commit_group;" ::: "memory")

// ---- tf32 helpers ---------------------------------------------------------
__device__ __forceinline__ void cvt_hilo(float raw, uint32_t& hi, uint32_t& lo) {
    asm("cvt.rna.tf32.f32 %0, %1;" : "=r"(hi) : "f"(raw));
    float rem = raw - __uint_as_float(hi);
    asm("cvt.rna.tf32.f32 %0, %1;" : "=r"(lo) : "f"(rem));
}
__device__ __forceinline__ void mma_tf32(float* d, const uint32_t* a,
                                         uint32_t b0, uint32_t b1) {
    asm volatile("mma.sync.aligned.m16n8k8.row.col.f32.tf32.tf32.f32 "
                 "{%0,%1,%2,%3}, {%4,%5,%6,%7}, {%8,%9}, {%0,%1,%2,%3};"
                 : "+f"(d[0]), "+f"(d[1]), "+f"(d[2]), "+f"(d[3])
                 : "r"(a[0]), "r"(a[1]), "r"(a[2]), "r"(a[3]),
                   "r"(b0), "r"(b1));
}

// ---------------------------------------------------------------------------
// weight split (all weights, one launch): hi = tf32(w), lo = tf32(w - hi)
// ---------------------------------------------------------------------------
__global__ void wsplit_all_kernel(const float* __restrict__ nW,
                                  const float* __restrict__ W1,
                                  const float* __restrict__ W2,
                                  float* __restrict__ whi,
                                  float* __restrict__ wlo) {
    int i = blockIdx.x * blockDim.x + threadIdx.x;
    if (i >= WSPLIT_TOTAL) return;
    float w;
    if (i < 16384)       w = nW[i];
    else if (i < 114688) w = W1[i - 16384];
    else                 w = W2[i - 114688];
    uint32_t hi, lo;
    cvt_hilo(w, hi, lo);
    whi[i] = __uint_as_float(hi);
    wlo[i] = __uint_as_float(lo);
}

// ---------------------------------------------------------------------------
// CSR build: (deg zeroed by cudaMemsetAsync) count -> scan -> fill
// ---------------------------------------------------------------------------
__global__ void count_kernel(const int* __restrict__ dst, int* __restrict__ deg) {
    int e = blockIdx.x * blockDim.x + threadIdx.x;
    if (e < EE) atomicAdd(&deg[dst[e]], 1);
}

__global__ __launch_bounds__(1024)
void scan_kernel(const int* __restrict__ deg, int* __restrict__ off,
                 int* __restrict__ cur) {
    __shared__ int part[1024];
    const int tid = threadIdx.x;
    const int per = (NN + 1023) / 1024;   // 40
    const int base = tid * per;
    int s = 0;
#pragma unroll 4
    for (int i = 0; i < per; i++) {
        const int n = base + i;
        if (n < NN) s += deg[n];
    }
    part[tid] = s;
    __syncthreads();
    for (int ofs = 1; ofs < 1024; ofs <<= 1) {
        int v = (tid >= ofs) ? part[tid - ofs] : 0;
        __syncthreads();
        part[tid] += v;
        __syncthreads();
    }
    int run = (tid > 0) ? part[tid - 1] : 0;   // exclusive prefix
    for (int i = 0; i < per; i++) {
        const int n = base + i;
        if (n < NN) {
            off[n] = run;
            cur[n] = run;
            run += deg[n];
        }
    }
    if (tid == 1023) off[NN] = EE;
}

__global__ void fill_kernel(const int* __restrict__ src,
                            const int* __restrict__ dst,
                            int* __restrict__ cur,
                            int* __restrict__ esrc,
                            int* __restrict__ eidx) {
    int e = blockIdx.x * blockDim.x + threadIdx.x;
    if (e >= EE) return;
    const int d = dst[e];
    const int p = atomicAdd(&cur[d], 1);
    esrc[p] = src[e];
    eidx[p] = e;
}

// ---------------------------------------------------------------------------
// prep: pre[n] = (h[n]·attn_W[0:128], h[n]·attn_W[128:256]). Warp per node.
// ---------------------------------------------------------------------------
__global__ __launch_bounds__(128)
void prep_kernel(const float* __restrict__ h,
                 const float* __restrict__ attn_W,   // [256]
                 float2* __restrict__ pre) {
    const int warp = (blockIdx.x * blockDim.x + threadIdx.x) >> 5;
    const int lane = threadIdx.x & 31;
    if (warp >= NN) return;
    const int d0 = lane * 4;
    const float4 hv = *(const float4*)(h + (size_t)warp * DD + d0);
    const float4 wi = *(const float4*)(attn_W + d0);
    const float4 wj = *(const float4*)(attn_W + DD + d0);
    float pi = hv.x * wi.x + hv.y * wi.y + hv.z * wi.z + hv.w * wi.w;
    float pj = hv.x * wj.x + hv.y * wj.y + hv.z * wj.z + hv.w * wj.w;
#pragma unroll
    for (int off = 16; off > 0; off >>= 1) {
        pi += __shfl_xor_sync(0xffffffffu, pi, off);
        pj += __shfl_xor_sync(0xffffffffu, pj, off);
    }
    if (lane == 0) pre[warp] = make_float2(pi, pj);
}

// ---------------------------------------------------------------------------
// per-edge accumulate (vmask applied after relu; operands always finite)
// ---------------------------------------------------------------------------
__device__ __forceinline__ void accum_edge(
    float4& acc, float a, float vmask, const float4 xj,
    const ulonglong2 qa, const ulonglong2 qb,
    const ulonglong2 qc, const ulonglong2 qd,
    const unsigned long long* __restrict__ wE2,
    const unsigned long long* __restrict__ ebp) {
    const unsigned long long ep[8] = {qa.x, qa.y, qb.x, qb.y,
                                      qc.x, qc.y, qd.x, qd.y};
    unsigned long long av0 = ebp[0], av1 = ebp[1], av2 = ebp[2], av3 = ebp[3];
#pragma unroll
    for (int k2 = 0; k2 < 8; k2++) {
        ffma2(av0, ep[k2], wE2[k2 * 4 + 0]);
        ffma2(av1, ep[k2], wE2[k2 * 4 + 1]);
        ffma2(av2, ep[k2], wE2[k2 * 4 + 2]);
        ffma2(av3, ep[k2], wE2[k2 * 4 + 3]);
    }
    acc.x = fmaf(fmaxf(fmaf(xj.x, a, fold2(av0)), 0.0f), vmask, acc.x);
    acc.y = fmaf(fmaxf(fmaf(xj.y, a, fold2(av1)), 0.0f), vmask, acc.y);
    acc.z = fmaf(fmaxf(fmaf(xj.z, a, fold2(av2)), 0.0f), vmask, acc.z);
    acc.w = fmaf(fmaxf(fmaf(xj.w, a, fold2(av3)), 0.0f), vmask, acc.w);
}

// ---------------------------------------------------------------------------
// CSR edge kernel v7: persistent warp-per-node with a DEEP (4-stage) smem
// pipeline. Per stage: 2 edges — h[src] gathered per-lane via cp.async (16B),
// ea rows via lanes 0-7. Registers hold only pre.y + mask rings.
// ---------------------------------------------------------------------------
__global__ __launch_bounds__(128, 3)
void edge_csr_kernel(const float* __restrict__ h,
                     const float* __restrict__ edge_attr,
                     const int* __restrict__ off,
                     const int* __restrict__ esrc,
                     const int* __restrict__ eidx,
                     const float* __restrict__ edge_W,   // [16,128]
                     const float* __restrict__ edge_b,   // [128]
                     const float2* __restrict__ pre,     // [N]
                     const float* __restrict__ attn_b,   // [1]
                     const float* __restrict__ eps_l,
                     float* __restrict__ agg) {
    __shared__ __align__(16) float hb[4][DST][2][DD];    // 16 KB
    __shared__ __align__(16) float eb_s[4][DST][2][EDD]; // 2 KB

    const int lane = threadIdx.x & 31;
    const int wwid = threadIdx.x >> 5;
    const int gwarp = (blockIdx.x * blockDim.x + threadIdx.x) >> 5;
    const int nwarp = (gridDim.x * blockDim.x) >> 5;
    const int d0 = lane * 4;

    unsigned long long wE2[32];
#pragma unroll
    for (int k2 = 0; k2 < 8; k2++) {
        const float4 wa = *(const float4*)(edge_W + (2 * k2) * DD + d0);
        const float4 wb = *(const float4*)(edge_W + (2 * k2 + 1) * DD + d0);
        wE2[k2 * 4 + 0] = pack2(wa.x, wb.x);
        wE2[k2 * 4 + 1] = pack2(wa.y, wb.y);
        wE2[k2 * 4 + 2] = pack2(wa.z, wb.z);
        wE2[k2 * 4 + 3] = pack2(wa.w, wb.w);
    }
    unsigned long long ebp[4];
    {
        const float4 eb = *(const float4*)(edge_b + d0);
        ebp[0] = pack2(eb.x, 0.0f); ebp[1] = pack2(eb.y, 0.0f);
        ebp[2] = pack2(eb.z, 0.0f); ebp[3] = pack2(eb.w, 0.0f);
    }
    const float ab = attn_b[0];
    const float s = 1.0f + eps_l[0];

    float pjA[DST], pjB[DST], mB[DST];

#pragma unroll 1
    for (int node = gwarp; node < NN; node += nwarp) {
        const int beg = off[node], end = off[node + 1];
        const float pd = __ldg(&pre[node].x) + ab;

        float4 acc;
        {
            const float4 hv = *(const float4*)(h + (size_t)node * DD + d0);
            acc.x = hv.x * s; acc.y = hv.y * s; acc.z = hv.z * s; acc.w = hv.w * s;
        }

        const int ne = end - beg;
        if (ne > 0) {
            const int nst = (ne + 1) >> 1;   // stages of 2 edges

            // ---- issue one stage st (slot st % DST) ----
#define ISSUE(st) { \
    const int _r = (st) % DST; \
    const int _j0 = beg + 2 * (st); \
    const int _jA = _j0; \
    const int _jB = (_j0 + 1 < end) ? _j0 + 1 : beg; \
    mB[_r] = (_j0 + 1 < end) ? 1.0f : 0.0f; \
    const int _sA = esrc[_jA], _iA = eidx[_jA]; \
    const int _sB = esrc[_jB], _iB = eidx[_jB]; \
    pjA[_r] = __ldg(&pre[_sA].y); \
    pjB[_r] = __ldg(&pre[_sB].y); \
    cp16(&hb[wwid][_r][0][d0], h + (size_t)_sA * DD + d0); \
    cp16(&hb[wwid][_r][1][d0], h + (size_t)_sB * DD + d0); \
    if (lane < 4)      cp16(&eb_s[wwid][_r][0][lane * 4], \
                            edge_attr + (size_t)_iA * EDD + lane * 4); \
    else if (lane < 8) cp16(&eb_s[wwid][_r][1][(lane - 4) * 4], \
                            edge_attr + (size_t)_iB * EDD + (lane - 4) * 4); \
    CP_COMMIT(); }

            // prologue: fill up to DST stages (pad with empty groups)
            const int npro = (nst < DST) ? nst : DST;
            for (int st = 0; st < npro; st++) ISSUE(st);
            for (int st = npro; st < DST; st++) CP_COMMIT();

#pragma unroll 1
            for (int it = 0; it < nst; it++) {
                asm volatile("cp.async.wait_group %0;" :: "n"(DST - 1) : "memory");
                __syncwarp();
                const int r = it % DST;

                const float4 xA = *(const float4*)&hb[wwid][r][0][d0];
                const float4 xB = *(const float4*)&hb[wwid][r][1][d0];
                const ulonglong2 qA0 = *(const ulonglong2*)&eb_s[wwid][r][0][0];
                const ulonglong2 qA1 = *(const ulonglong2*)&eb_s[wwid][r][0][4];
                const ulonglong2 qA2 = *(const ulonglong2*)&eb_s[wwid][r][0][8];
                const ulonglong2 qA3 = *(const ulonglong2*)&eb_s[wwid][r][0][12];
                const ulonglong2 qB0 = *(const ulonglong2*)&eb_s[wwid][r][1][0];
                const ulonglong2 qB1 = *(const ulonglong2*)&eb_s[wwid][r][1][4];
                const ulonglong2 qB2 = *(const ulonglong2*)&eb_s[wwid][r][1][8];
                const ulonglong2 qB3 = *(const ulonglong2*)&eb_s[wwid][r][1][12];
                const float aA = 1.0f / (1.0f + __expf(-(pd + pjA[r])));
                const float aB = 1.0f / (1.0f + __expf(-(pd + pjB[r])));
                accum_edge(acc, aA, 1.0f,  xA, qA0, qA1, qA2, qA3, wE2, ebp);
                accum_edge(acc, aB, mB[r], xB, qB0, qB1, qB2, qB3, wE2, ebp);

                __syncwarp();   // all lanes done reading slot r before refill
                if (it + DST < nst) { ISSUE(it + DST); }
                else               { CP_COMMIT(); }
            }
#undef ISSUE
        }

        *(float4*)(agg + (size_t)node * DD + d0) = acc;
    }
}

// ---------------------------------------------------------------------------
// 3xTF32 tensor-core GEMM (R15 verbatim): B pre-split hi/lo, 256 threads,
// 128x128 tile, warp tile 32x64, A ring 3 stages / B rings 4 stages.
// ---------------------------------------------------------------------------
__global__ __launch_bounds__(256, 2)
void tgemm_kernel(const float* __restrict__ A,
                  const float* __restrict__ Bhi, const float* __restrict__ Blo,
                  const float* __restrict__ bias,
                  const float* __restrict__ bn_g, const float* __restrict__ bn_b,
                  float* __restrict__ C,
                  int M, int K, int Nc, int do_relu, int do_bn) {
    __shared__ __align__(16) float As[3][8][136];
    __shared__ __align__(16) float Bh[4][8][136];
    __shared__ __align__(16) float Bl[4][8][136];

    const int tid = threadIdx.x;
    const int wid = tid >> 5;
    const int lane = tid & 31;
    const int gID = lane >> 2;
    const int tIG = lane & 3;
    const int warp_m = wid >> 1;
    const int warp_n = wid & 1;
    const int row0 = blockIdx.y * 128;
    const int col0 = blockIdx.x * 128;

    const int a_row = tid >> 1;
    const int a_col = (tid & 1) * 4;
    const int b_row = tid >> 5;
    const int b_col = lane * 4;

    const int gr = row0 + a_row;
    const bool av = gr < M;
    const float* aptr  = A   + (size_t)gr * K + a_col;
    const float* bhptr = Bhi + (size_t)b_row * Nc + col0 + b_col;
    const float* blptr = Blo + (size_t)b_row * Nc + col0 + b_col;

    const int nt = K >> 3;
    const float4 f40 = make_float4(0.f, 0.f, 0.f, 0.f);
    float4 ar;

#define LDG_A(k0) { ar = av ? *(const float4*)(aptr + (k0)) : f40; }
#define STS_A(stg) { As[stg][a_col+0][a_row] = ar.x; As[stg][a_col+1][a_row] = ar.y; \
                     As[stg][a_col+2][a_row] = ar.z; As[stg][a_col+3][a_row] = ar.w; }
#define CP_B(stg, k0) { \
    uint32_t _dh = (uint32_t)__cvta_generic_to_shared(&Bh[stg][b_row][b_col]); \
    uint32_t _dl = (uint32_t)__cvta_generic_to_shared(&Bl[stg][b_row][b_col]); \
    const float* _sh = bhptr + (size_t)(k0) * Nc; \
    const float* _sl = blptr + (size_t)(k0) * Nc; \
    asm volatile("cp.async.cg.shared.global [%0], [%1], 16;\n\t" \
                 "cp.async.cg.shared.global [%2], [%3], 16;\n\t" \
                 "cp.async.commit_group;\n" \
                 :: "r"(_dh), "l"(_sh), "r"(_dl), "l"(_sl) : "memory"); }

    float acc[2][8][4];
#pragma unroll
    for (int i = 0; i < 2; i++)
#pragma unroll
        for (int jj = 0; jj < 8; jj++)
#pragma unroll
            for (int c = 0; c < 4; c++) acc[i][jj][c] = 0.0f;

    LDG_A(0); CP_B(0, 0); STS_A(0);
    LDG_A(8); CP_B(1, 8);

#pragma unroll 1
    for (int t = 0; t < nt; t++) {
        const int sa = t % 3;
        const int sb = t & 3;
        if (t + 1 < nt) STS_A((t + 1) % 3);
        if (t + 2 < nt) { const int k0 = (t + 2) * 8; LDG_A(k0); CP_B((t + 2) & 3, k0); }
        const int rem = nt - 1 - t;
        if (rem >= 2)      asm volatile("cp.async.wait_group 2;" ::: "memory");
        else if (rem == 1) asm volatile("cp.async.wait_group 1;" ::: "memory");
        else               asm volatile("cp.async.wait_group 0;" ::: "memory");
        __syncthreads();

        uint32_t Ah[2][4], Al[2][4];
#pragma unroll
        for (int i = 0; i < 2; i++) {
            const int rb = warp_m * 32 + i * 16 + gID;
            const float r0 = As[sa][tIG    ][rb];
            const float r1 = As[sa][tIG    ][rb + 8];
            const float r2 = As[sa][tIG + 4][rb];
            const float r3 = As[sa][tIG + 4][rb + 8];
            cvt_hilo(r0, Ah[i][0], Al[i][0]);
            cvt_hilo(r1, Ah[i][1], Al[i][1]);
            cvt_hilo(r2, Ah[i][2], Al[i][2]);
            cvt_hilo(r3, Ah[i][3], Al[i][3]);
        }
#pragma unroll
        for (int jn = 0; jn < 8; jn++) {
            const int cb = warp_n * 64 + jn * 8 + gID;
            const uint32_t bh0 = __float_as_uint(Bh[sb][tIG    ][cb]);
            const uint32_t bh1 = __float_as_uint(Bh[sb][tIG + 4][cb]);
            const uint32_t bl0 = __float_as_uint(Bl[sb][tIG    ][cb]);
            const uint32_t bl1 = __float_as_uint(Bl[sb][tIG + 4][cb]);
#pragma unroll
            for (int i = 0; i < 2; i++) {
                mma_tf32(acc[i][jn], Ah[i], bh0, bh1);
                mma_tf32(acc[i][jn], Ah[i], bl0, bl1);
                mma_tf32(acc[i][jn], Al[i], bh0, bh1);
            }
        }
    }

#pragma unroll
    for (int i = 0; i < 2; i++) {
        const int r_lo = row0 + warp_m * 32 + i * 16 + gID;
        const int r_hi = r_lo + 8;
#pragma unroll
        for (int jn = 0; jn < 8; jn++) {
            const int c = col0 + warp_n * 64 + jn * 8 + tIG * 2;
            const float b0v = bias[c], b1v = bias[c + 1];
            float v00 = acc[i][jn][0] + b0v;
            float v01 = acc[i][jn][1] + b1v;
            float v10 = acc[i][jn][2] + b0v;
            float v11 = acc[i][jn][3] + b1v;
            if (do_bn) {
                const float g0 = bn_g[c] * BN_INV, g1 = bn_g[c + 1] * BN_INV;
                const float bb0 = bn_b[c], bb1 = bn_b[c + 1];
                v00 = fmaf(g0, v00, bb0); v01 = fmaf(g1, v01, bb1);
                v10 = fmaf(g0, v10, bb0); v11 = fmaf(g1, v11, bb1);
            }
            if (do_relu) {
                v00 = fmaxf(v00, 0.0f); v01 = fmaxf(v01, 0.0f);
                v10 = fmaxf(v10, 0.0f); v11 = fmaxf(v11, 0.0f);
            }
            if (r_lo < M) *(float2*)(C + (size_t)r_lo * Nc + c) = make_float2(v00, v01);
            if (r_hi < M) *(float2*)(C + (size_t)r_hi * Nc + c) = make_float2(v10, v11);
        }
    }
#undef LDG_A
#undef STS_A
#undef CP_B
}

// ---------------------------------------------------------------------------
extern "C" void kernel_launch(void* const* d_in, const int* in_sizes, int n_in,
                              void* d_out, int out_size) {
    const float* x         = (const float*)d_in[0];
    const float* edge_attr = (const float*)d_in[1];
    const float* node_W    = (const float*)d_in[2];
    const float* node_b    = (const float*)d_in[3];
    const float* edge_W    = (const float*)d_in[4];
    const float* edge_b    = (const float*)d_in[5];
    const float* attn_W    = (const float*)d_in[6];
    const float* attn_b    = (const float*)d_in[7];
    const float* eps       = (const float*)d_in[8];
    const float* W1        = (const float*)d_in[9];
    const float* b1        = (const float*)d_in[10];
    const float* bn1_g     = (const float*)d_in[11];
    const float* bn1_b     = (const float*)d_in[12];
    const float* W2        = (const float*)d_in[13];
    const float* b2        = (const float*)d_in[14];
    const float* bn_g      = (const float*)d_in[15];
    const float* bn_b      = (const float*)d_in[16];
    const int*   edge_index= (const int*)d_in[17];

    float *hA, *hB, *agg, *tbuf, *whi, *wlo; float2* pre;
    int *deg, *off, *cur, *esrc, *eidx;
    cudaGetSymbolAddress((void**)&hA,   g_h);
    cudaGetSymbolAddress((void**)&hB,   g_h2);
    cudaGetSymbolAddress((void**)&agg,  g_agg);
    cudaGetSymbolAddress((void**)&tbuf, g_t);
    cudaGetSymbolAddress((void**)&pre,  g_pre);
    cudaGetSymbolAddress((void**)&deg,  g_deg);
    cudaGetSymbolAddress((void**)&off,  g_off);
    cudaGetSymbolAddress((void**)&cur,  g_cur);
    cudaGetSymbolAddress((void**)&esrc, g_esrc);
    cudaGetSymbolAddress((void**)&eidx, g_eidx);
    cudaGetSymbolAddress((void**)&whi,  g_whi);
    cudaGetSymbolAddress((void**)&wlo,  g_wlo);

    const int* src_arr = edge_index;
    const int* dst_arr = edge_index + EE;
    const int mblk = (NN + 127) / 128;     // 313

    const int W1_OFF = 16384;
    const int W2_OFF = 114688;

    // Weight split (single launch)
    wsplit_all_kernel<<<(WSPLIT_TOTAL + 255) / 256, 256>>>(node_W, W1, W2, whi, wlo);

    // CSR build (deg zeroed via memset node — graph-capturable)
    cudaMemsetAsync(deg, 0, NN * sizeof(int));
    count_kernel<<<(EE + 255) / 256, 256>>>(dst_arr, deg);
    scan_kernel<<<1, 1024>>>(deg, off, cur);
    fill_kernel<<<(EE + 255) / 256, 256>>>(src_arr, dst_arr, cur, esrc, eidx);

    // node encoder: h = x @ node_W + node_b
    tgemm_kernel<<<dim3(1, mblk), 256>>>(x, whi, wlo, node_b, nullptr, nullptr,
                                         hA, NN, DD, DD, 0, 0);

    const float* hcur = hA;
    float* hnext = hB;
    for (int l = 0; l < LL; l++) {
        prep_kernel<<<10000, 128>>>(hcur, attn_W + (size_t)l * 2 * DD, pre);
        edge_csr_kernel<<<444, 128>>>(hcur, edge_attr, off, esrc, eidx,
                                      edge_W + (size_t)l * EDD * DD,
                                      edge_b + (size_t)l * DD,
                                      pre, attn_b + l, eps + l, agg);
        // t = relu(bn1(agg @ W1 + b1))   [N,128]@[128,256]
        tgemm_kernel<<<dim3(2, mblk), 256>>>(agg,
                                             whi + W1_OFF + (size_t)l * 32768,
                                             wlo + W1_OFF + (size_t)l * 32768,
                                             b1 + (size_t)l * 2 * DD,
                                             bn1_g + (size_t)l * 2 * DD,
                                             bn1_b + (size_t)l * 2 * DD,
                                             tbuf, NN, DD, 2 * DD, 1, 1);
        // h' = [relu] bn(t @ W2 + b2)    [N,256]@[256,128]
        float* outp = (l == LL - 1) ? (float*)d_out : hnext;
        tgemm_kernel<<<dim3(1, mblk), 256>>>(tbuf,
                                             whi + W2_OFF + (size_t)l * 32768,
                                             wlo + W2_OFF + (size_t)l * 32768,
                                             b2 + (size_t)l * DD,
                                             bn_g + (size_t)l * DD,
                                             bn_b + (size_t)l * DD,
                                             outp, NN, 2 * DD, DD, (l < LL - 1) ? 1 : 0, 1);
        if (l < LL - 1) {
            hcur = outp;
            hnext = (outp == hA) ? hB : hA;
        }
    }
}